// round 14
// baseline (speedup 1.0000x reference)
#include <cuda_runtime.h>
#include <cuda_fp16.h>
#include <stdint.h>

#define NNODES 100000
#define FDIM   64
#define EMAX   2000000   // reference uses E=1.6M; headroom

#define SCAN_BLK   1024
#define NSCANBLK   ((NNODES + SCAN_BLK - 1) / SCAN_BLK)   // 98

// ---------------------------------------------------------------------------
// Static device scratch (no allocation allowed anywhere)
// ---------------------------------------------------------------------------
__device__ __align__(16) __half g_hh[(size_t)NNODES * FDIM];  // 12.8 MB (h, fp16)
__device__ __align__(16) __half g_ah[(size_t)NNODES * FDIM];  // 12.8 MB (act, fp16)
__device__ float g_dinv[NNODES];
__device__ int   g_degi[NNODES];
__device__ int   g_off[NNODES + 1];
__device__ int   g_cursor[NNODES];
__device__ int   g_flagz[NSCANBLK];   // 0=invalid 1=aggregate 2=prefix
__device__ int   g_aggv[NSCANBLK];
__device__ int   g_prefv[NSCANBLK];
__device__ __align__(16) int2 g_csr[EMAX];  // {src, bitcast(dinv[src])} 16 MB

// ---------------------------------------------------------------------------
// histogram of in-edges (int atomics, exact). edge_index int32, [2, E].
// ---------------------------------------------------------------------------
__global__ void hist_kernel(const int* __restrict__ ei, long long E) {
    long long stride = (long long)gridDim.x * blockDim.x;
    for (long long e = (long long)blockIdx.x * blockDim.x + threadIdx.x;
         e < E; e += stride)
        atomicAdd(&g_degi[ei[E + e]], 1);
}

// ---------------------------------------------------------------------------
// Single-kernel exclusive scan (decoupled lookback), fused dinv.
// 98 blocks x 1024 threads; all blocks resident in wave 1 -> spin is safe.
// ---------------------------------------------------------------------------
__global__ __launch_bounds__(SCAN_BLK) void scan_kernel() {
    __shared__ int warp_part[SCAN_BLK / 32];   // 32
    __shared__ int s_prefix;
    const int b    = blockIdx.x;
    const int tid  = threadIdx.x;
    const int lane = tid & 31;
    const int wid  = tid >> 5;
    const int i    = b * SCAN_BLK + tid;

    int v = 0;
    if (i < NNODES) {
        v = g_degi[i];
        g_dinv[i] = rsqrtf((float)v + 1.0f);   // fused dinv
    }

    // inclusive warp scan
    int sc = v;
#pragma unroll
    for (int o = 1; o < 32; o <<= 1) {
        int t = __shfl_up_sync(0xffffffffu, sc, o);
        if (lane >= o) sc += t;
    }
    if (lane == 31) warp_part[wid] = sc;
    __syncthreads();
    if (wid == 0) {
        int ws = warp_part[lane];
#pragma unroll
        for (int o = 1; o < 32; o <<= 1) {
            int t = __shfl_up_sync(0xffffffffu, ws, o);
            if (lane >= o) ws += t;
        }
        warp_part[lane] = ws;
    }
    __syncthreads();
    const int block_incl  = sc + (wid > 0 ? warp_part[wid - 1] : 0);
    const int block_total = warp_part[31];

    // decoupled lookback (thread 0)
    if (tid == 0) {
        int run = 0;
        if (b == 0) {
            g_aggv[0]  = block_total;
            g_prefv[0] = 0;
            __threadfence();
            atomicExch(&g_flagz[0], 2);
        } else {
            g_aggv[b] = block_total;
            __threadfence();
            atomicExch(&g_flagz[b], 1);
            int j = b - 1;
            while (true) {
                int f;
                do { f = atomicAdd(&g_flagz[j], 0); } while (f == 0);
                if (f == 2) { run += g_prefv[j] + g_aggv[j]; break; }
                run += g_aggv[j];
                j--;
            }
            g_prefv[b] = run;
            __threadfence();
            atomicExch(&g_flagz[b], 2);
        }
        s_prefix = run;
    }
    __syncthreads();
    const int pre = s_prefix;
    if (i < NNODES) {
        int off = pre + block_incl - v;   // exclusive
        g_off[i]    = off;
        g_cursor[i] = off;
    }
    if (b == NSCANBLK - 1 && tid == 0)
        g_off[NNODES] = pre + block_total;
}

// ---------------------------------------------------------------------------
// CSR fill: csr[pos] = {src, dinv[src]}  (packed 8B write per edge)
// ---------------------------------------------------------------------------
__global__ void fill_kernel(const int* __restrict__ ei, long long E) {
    long long stride = (long long)gridDim.x * blockDim.x;
    for (long long e = (long long)blockIdx.x * blockDim.x + threadIdx.x;
         e < E; e += stride) {
        int s = ei[e];
        int d = ei[E + e];
        int pos = atomicAdd(&g_cursor[d], 1);
        g_csr[pos] = make_int2(s, __float_as_int(g_dinv[s]));
    }
}

// ---------------------------------------------------------------------------
// Aggregation + epilogue (fp16 gather, fp32 accumulate), software-pipelined:
//   out[node] = relu( dinv[n]*(sum_e dinv[s] h[s] + dinv[n] h[n]) + b )
// One warp per node; 4 quarters x 8 lanes, LDG.128 per edge row.
// Next batch's CSR + row loads issue before current batch accumulates.
// ---------------------------------------------------------------------------
template <typename OutT>
__global__ __launch_bounds__(256) void agg_kernel(
    const __half* __restrict__ h, const float* __restrict__ bias,
    OutT* __restrict__ outv)
{
    const int lane = threadIdx.x & 31;
    const int eq   = lane >> 3;     // edge slot within quad: 0..3
    const int fl   = lane & 7;      // feature octet: halves [fl*8, fl*8+8)
    const int gwarp = (blockIdx.x * blockDim.x + threadIdx.x) >> 5;
    const int nwarp = (gridDim.x * blockDim.x) >> 5;

    const float4 b0 = reinterpret_cast<const float4*>(bias)[fl * 2];
    const float4 b1 = reinterpret_cast<const float4*>(bias)[fl * 2 + 1];

    for (int node = gwarp; node < NNODES; node += nwarp) {
        const int beg = g_off[node];
        const int end = g_off[node + 1];
        const float di = g_dinv[node];

        float acc[8];
        if (eq == 0) {   // self-loop handled by quarter 0
            uint4 sv = *reinterpret_cast<const uint4*>(
                h + (size_t)node * FDIM + fl * 8);
            const __half2* hp = reinterpret_cast<const __half2*>(&sv);
#pragma unroll
            for (int p = 0; p < 4; p++) {
                float2 f = __half22float2(hp[p]);
                acc[2 * p]     = di * f.x;
                acc[2 * p + 1] = di * f.y;
            }
        } else {
#pragma unroll
            for (int p = 0; p < 8; p++) acc[p] = 0.f;
        }

        // -------- software-pipelined main loop: 8 edges per stage --------
        int base = beg;
        bool have = (base + 8 <= end);
        int2 e0, e1; uint4 v0, v1;
        if (have) {
            e0 = g_csr[base + eq];
            e1 = g_csr[base + 4 + eq];
            v0 = *reinterpret_cast<const uint4*>(
                h + (size_t)e0.x * FDIM + fl * 8);
            v1 = *reinterpret_cast<const uint4*>(
                h + (size_t)e1.x * FDIM + fl * 8);
        }
        while (have) {
            const int nb = base + 8;
            const bool nhave = (nb + 8 <= end);
            int2 ne0, ne1; uint4 nv0, nv1;
            if (nhave) {                     // prefetch next batch
                ne0 = g_csr[nb + eq];
                ne1 = g_csr[nb + 4 + eq];
                nv0 = *reinterpret_cast<const uint4*>(
                    h + (size_t)ne0.x * FDIM + fl * 8);
                nv1 = *reinterpret_cast<const uint4*>(
                    h + (size_t)ne1.x * FDIM + fl * 8);
            }
            const float w0 = __int_as_float(e0.y);
            const float w1 = __int_as_float(e1.y);
            const __half2* p0 = reinterpret_cast<const __half2*>(&v0);
            const __half2* p1 = reinterpret_cast<const __half2*>(&v1);
#pragma unroll
            for (int p = 0; p < 4; p++) {
                float2 f0 = __half22float2(p0[p]);
                float2 f1 = __half22float2(p1[p]);
                acc[2 * p]     = fmaf(w0, f0.x, acc[2 * p]);
                acc[2 * p + 1] = fmaf(w0, f0.y, acc[2 * p + 1]);
                acc[2 * p]     = fmaf(w1, f1.x, acc[2 * p]);
                acc[2 * p + 1] = fmaf(w1, f1.y, acc[2 * p + 1]);
            }
            base = nb;
            have = nhave;
            if (nhave) { e0 = ne0; e1 = ne1; v0 = nv0; v1 = nv1; }
        }
        // -------- remainder: up to 7 edges, 4 at a time, zero-padded -----
        for (; base < end; base += 4) {
            int idx = base + eq;
            int2 ez = g_csr[idx < end ? idx : (end - 1)];
            float wz = (idx < end) ? __int_as_float(ez.y) : 0.f;
            uint4 vz = *reinterpret_cast<const uint4*>(
                h + (size_t)ez.x * FDIM + fl * 8);
            const __half2* pz = reinterpret_cast<const __half2*>(&vz);
#pragma unroll
            for (int p = 0; p < 4; p++) {
                float2 fz = __half22float2(pz[p]);
                acc[2 * p]     = fmaf(wz, fz.x, acc[2 * p]);
                acc[2 * p + 1] = fmaf(wz, fz.y, acc[2 * p + 1]);
            }
        }

#pragma unroll
        for (int p = 0; p < 8; p++) {
            acc[p] += __shfl_xor_sync(0xffffffffu, acc[p], 8);
            acc[p] += __shfl_xor_sync(0xffffffffu, acc[p], 16);
        }

        if (eq == 0) {   // lanes 0..7 write the 64-float row
            float r[8];
            r[0] = fmaxf(fmaf(acc[0], di, b0.x), 0.f);
            r[1] = fmaxf(fmaf(acc[1], di, b0.y), 0.f);
            r[2] = fmaxf(fmaf(acc[2], di, b0.z), 0.f);
            r[3] = fmaxf(fmaf(acc[3], di, b0.w), 0.f);
            r[4] = fmaxf(fmaf(acc[4], di, b1.x), 0.f);
            r[5] = fmaxf(fmaf(acc[5], di, b1.y), 0.f);
            r[6] = fmaxf(fmaf(acc[6], di, b1.z), 0.f);
            r[7] = fmaxf(fmaf(acc[7], di, b1.w), 0.f);
            if constexpr (sizeof(OutT) == 2) {   // fp16 activations
                union { __half2 hx[4]; uint4 u; } pk;
                pk.hx[0] = __floats2half2_rn(r[0], r[1]);
                pk.hx[1] = __floats2half2_rn(r[2], r[3]);
                pk.hx[2] = __floats2half2_rn(r[4], r[5]);
                pk.hx[3] = __floats2half2_rn(r[6], r[7]);
                *reinterpret_cast<uint4*>(
                    (__half*)outv + (size_t)node * FDIM + fl * 8) = pk.u;
            } else {                             // fp32 final output
                float4* o = reinterpret_cast<float4*>(
                    (float*)outv + (size_t)node * FDIM + fl * 8);
                o[0] = make_float4(r[0], r[1], r[2], r[3]);
                o[1] = make_float4(r[4], r[5], r[6], r[7]);
            }
        }
    }
}

// ---------------------------------------------------------------------------
// Tensor-core GEMM: C[n,64] = A[n,64] @ W[64,64]
// fp16 inputs (A converted on stage), fp32 accumulate, fp16 output.
// 256 threads / 256 rows per block; warp = 32 rows (2 m16 tiles).
// ---------------------------------------------------------------------------
#define GROWS 256

template <typename InT>
__global__ __launch_bounds__(256) void gemm_mma_kernel(
    const InT* __restrict__ A, const float* __restrict__ W,
    __half* __restrict__ C, int n_rows)
{
    __shared__ __half sA[GROWS * 72];    // 36864 B
    __shared__ __half sWT[64 * 72];      // 9216 B (WT[n][k] = W[k][n])

    const int tid  = threadIdx.x;
    const int row0 = blockIdx.x * GROWS;

    // stage WT (fp16, transposed)
    for (int idx = tid; idx < 4096; idx += 256) {
        int k = idx >> 6, n = idx & 63;
        sWT[n * 72 + k] = __float2half_rn(W[idx]);
    }

    // stage A (fp16): 256 rows x 32 half2
    for (int i = tid; i < GROWS * 32; i += 256) {
        int r   = i >> 5;
        int c2  = i & 31;
        int row = row0 + r;
        __half2 hv = __floats2half2_rn(0.f, 0.f);
        if (row < n_rows) {
            if constexpr (sizeof(InT) == 2) {
                hv = *reinterpret_cast<const __half2*>(
                    reinterpret_cast<const __half*>(A)
                    + (size_t)row * FDIM + c2 * 2);
            } else {
                float2 f = *reinterpret_cast<const float2*>(
                    reinterpret_cast<const float*>(A)
                    + (size_t)row * FDIM + c2 * 2);
                hv = __floats2half2_rn(f.x, f.y);
            }
        }
        *reinterpret_cast<__half2*>(&sA[r * 72 + c2 * 2]) = hv;
    }
    __syncthreads();

    const int lane = tid & 31;
    const int warp = tid >> 5;
    const int r    = lane >> 2;     // 0..7
    const int cq   = lane & 3;      // 0..3
    const int wrow = warp * 32;

    uint32_t afr[2][4][4];
#pragma unroll
    for (int mt = 0; mt < 2; mt++) {
        int rm = wrow + mt * 16;
#pragma unroll
        for (int kc = 0; kc < 4; kc++) {
            int kb = kc * 16;
            afr[mt][kc][0] = *reinterpret_cast<const uint32_t*>(
                &sA[(rm + r) * 72 + kb + cq * 2]);
            afr[mt][kc][1] = *reinterpret_cast<const uint32_t*>(
                &sA[(rm + r + 8) * 72 + kb + cq * 2]);
            afr[mt][kc][2] = *reinterpret_cast<const uint32_t*>(
                &sA[(rm + r) * 72 + kb + cq * 2 + 8]);
            afr[mt][kc][3] = *reinterpret_cast<const uint32_t*>(
                &sA[(rm + r + 8) * 72 + kb + cq * 2 + 8]);
        }
    }

#pragma unroll
    for (int nt = 0; nt < 8; nt++) {
        int nb = nt * 8;
        float acc[2][4] = {{0.f, 0.f, 0.f, 0.f}, {0.f, 0.f, 0.f, 0.f}};
#pragma unroll
        for (int kc = 0; kc < 4; kc++) {
            int kb = kc * 16;
            uint32_t b0 = *reinterpret_cast<const uint32_t*>(
                &sWT[(nb + r) * 72 + kb + cq * 2]);
            uint32_t b1 = *reinterpret_cast<const uint32_t*>(
                &sWT[(nb + r) * 72 + kb + cq * 2 + 8]);
#pragma unroll
            for (int mt = 0; mt < 2; mt++) {
                asm volatile(
                    "mma.sync.aligned.m16n8k16.row.col.f32.f16.f16.f32 "
                    "{%0,%1,%2,%3}, {%4,%5,%6,%7}, {%8,%9}, {%0,%1,%2,%3};"
                    : "+f"(acc[mt][0]), "+f"(acc[mt][1]),
                      "+f"(acc[mt][2]), "+f"(acc[mt][3])
                    : "r"(afr[mt][kc][0]), "r"(afr[mt][kc][1]),
                      "r"(afr[mt][kc][2]), "r"(afr[mt][kc][3]),
                      "r"(b0), "r"(b1));
            }
        }
#pragma unroll
        for (int mt = 0; mt < 2; mt++) {
            int row = row0 + wrow + mt * 16 + r;
            int col = nb + cq * 2;
            if (row < n_rows)
                *reinterpret_cast<__half2*>(C + (size_t)row * FDIM + col) =
                    __floats2half2_rn(acc[mt][0], acc[mt][1]);
            if (row + 8 < n_rows)
                *reinterpret_cast<__half2*>(C + (size_t)(row + 8) * FDIM + col) =
                    __floats2half2_rn(acc[mt][2], acc[mt][3]);
        }
    }
}

// ---------------------------------------------------------------------------
extern "C" void kernel_launch(void* const* d_in, const int* in_sizes, int n_in,
                              void* d_out, int out_size)
{
    const float* x  = (const float*)d_in[0];
    const int*   ei = (const int*)d_in[1];     // int32 (JAX x64 disabled)
    const float* W1 = (const float*)d_in[2];
    const float* b1 = (const float*)d_in[3];
    const float* W2 = (const float*)d_in[4];
    const float* b2 = (const float*)d_in[5];
    float* out = (float*)d_out;

    const long long E = (long long)in_sizes[1] / 2;

    __half* g_hh_ptr;   cudaGetSymbolAddress((void**)&g_hh_ptr,   g_hh);
    __half* g_ah_ptr;   cudaGetSymbolAddress((void**)&g_ah_ptr,   g_ah);
    int*    g_degi_ptr; cudaGetSymbolAddress((void**)&g_degi_ptr, g_degi);
    int*    g_flag_ptr; cudaGetSymbolAddress((void**)&g_flag_ptr, g_flagz);

    const int SMS = 148;
    dim3 blk(256);

    const int gemm_grid = (NNODES + GROWS - 1) / GROWS;   // 391
    const int agg_grid  = SMS * 24;

    // ---- CSR build ----
    cudaMemsetAsync(g_degi_ptr, 0, NNODES * sizeof(int));
    cudaMemsetAsync(g_flag_ptr, 0, NSCANBLK * sizeof(int));
    hist_kernel<<<SMS * 8, blk>>>(ei, E);
    scan_kernel<<<NSCANBLK, SCAN_BLK>>>();   // scan + dinv, single launch
    fill_kernel<<<SMS * 8, blk>>>(ei, E);

    // ---- layer 1 ----
    gemm_mma_kernel<float><<<gemm_grid, blk>>>(x, W1, g_hh_ptr, NNODES);
    agg_kernel<__half><<<agg_grid, blk>>>(g_hh_ptr, b1, g_ah_ptr);

    // ---- layer 2 ----
    gemm_mma_kernel<__half><<<gemm_grid, blk>>>(g_ah_ptr, W2, g_hh_ptr, NNODES);
    agg_kernel<float><<<agg_grid, blk>>>(g_hh_ptr, b2, out);
}

// round 15
// speedup vs baseline: 1.1574x; 1.1574x over previous
#include <cuda_runtime.h>
#include <cuda_fp16.h>
#include <stdint.h>

#define NNODES 100000
#define FDIM   64
#define EMAX   2000000   // reference uses E=1.6M; headroom

#define SCAN_BLK   1024
#define NSCANBLK   ((NNODES + SCAN_BLK - 1) / SCAN_BLK)   // 98

// ---------------------------------------------------------------------------
// Static device scratch (no allocation allowed anywhere)
// ---------------------------------------------------------------------------
__device__ __align__(16) __half g_hh[(size_t)NNODES * FDIM];  // 12.8 MB (h, fp16)
__device__ __align__(16) __half g_ah[(size_t)NNODES * FDIM];  // 12.8 MB (act, fp16)
__device__ float g_dinv[NNODES];
__device__ int   g_degi[NNODES];
__device__ int   g_off[NNODES + 1];
__device__ int   g_cursor[NNODES];
__device__ int   g_flagz[NSCANBLK];   // 0=invalid 1=aggregate 2=prefix
__device__ int   g_aggv[NSCANBLK];
__device__ int   g_prefv[NSCANBLK];
__device__ __align__(16) int2 g_csr[EMAX];  // {src, bitcast(dinv[src])} 16 MB

// ---------------------------------------------------------------------------
// histogram of in-edges (int atomics, exact). edge_index int32, [2, E].
// ---------------------------------------------------------------------------
__global__ void hist_kernel(const int* __restrict__ ei, long long E) {
    long long stride = (long long)gridDim.x * blockDim.x;
    for (long long e = (long long)blockIdx.x * blockDim.x + threadIdx.x;
         e < E; e += stride)
        atomicAdd(&g_degi[ei[E + e]], 1);
}

// ---------------------------------------------------------------------------
// Single-kernel exclusive scan, decoupled lookback with WARP-PARALLEL window
// (32 predecessors per step -> <=4 windows for 98 blocks). Fused dinv.
// All 98 blocks resident in wave 1 (<148 SMs) -> spinning is deadlock-free.
// ---------------------------------------------------------------------------
__global__ __launch_bounds__(SCAN_BLK) void scan_kernel() {
    __shared__ int warp_part[SCAN_BLK / 32];   // 32
    __shared__ int s_prefix;
    const int b    = blockIdx.x;
    const int tid  = threadIdx.x;
    const int lane = tid & 31;
    const int wid  = tid >> 5;
    const int i    = b * SCAN_BLK + tid;

    int v = 0;
    if (i < NNODES) {
        v = g_degi[i];
        g_dinv[i] = rsqrtf((float)v + 1.0f);   // fused dinv
    }

    // inclusive warp scan
    int sc = v;
#pragma unroll
    for (int o = 1; o < 32; o <<= 1) {
        int t = __shfl_up_sync(0xffffffffu, sc, o);
        if (lane >= o) sc += t;
    }
    if (lane == 31) warp_part[wid] = sc;
    __syncthreads();
    if (wid == 0) {
        int ws = warp_part[lane];
#pragma unroll
        for (int o = 1; o < 32; o <<= 1) {
            int t = __shfl_up_sync(0xffffffffu, ws, o);
            if (lane >= o) ws += t;
        }
        warp_part[lane] = ws;
    }
    __syncthreads();
    const int block_incl  = sc + (wid > 0 ? warp_part[wid - 1] : 0);
    const int block_total = warp_part[31];

    // publish aggregate, then warp 0 does parallel lookback
    if (wid == 0) {
        if (lane == 0) {
            g_aggv[b] = block_total;
            if (b == 0) g_prefv[0] = 0;
            __threadfence();
            atomicExch(&g_flagz[b], b == 0 ? 2 : 1);
        }
        int run = 0;
        if (b > 0) {
            int j = b - 1;
            while (true) {
                const int idx = j - lane;      // lane 0 = nearest predecessor
                int f = 0, val = 0;
                if (idx >= 0) {
                    do { f = atomicAdd(&g_flagz[idx], 0); } while (f == 0);
                    val = (f == 2)
                        ? atomicAdd(&g_prefv[idx], 0) + atomicAdd(&g_aggv[idx], 0)
                        : atomicAdd(&g_aggv[idx], 0);
                }
                const unsigned pm =
                    __ballot_sync(0xffffffffu, idx >= 0 && f == 2);
                const int firstP = pm ? (__ffs(pm) - 1) : 32;
                int contrib = (idx >= 0 && lane <= firstP) ? val : 0;
#pragma unroll
                for (int o = 16; o > 0; o >>= 1)
                    contrib += __shfl_down_sync(0xffffffffu, contrib, o);
                run += __shfl_sync(0xffffffffu, contrib, 0);
                if (firstP < 32) break;        // found a full prefix
                j -= 32;
            }
            if (lane == 0) {
                g_prefv[b] = run;
                __threadfence();
                atomicExch(&g_flagz[b], 2);
            }
        }
        if (lane == 0) s_prefix = run;
    }
    __syncthreads();
    const int pre = s_prefix;
    if (i < NNODES) {
        int off = pre + block_incl - v;   // exclusive
        g_off[i]    = off;
        g_cursor[i] = off;
    }
    if (b == NSCANBLK - 1 && tid == 0)
        g_off[NNODES] = pre + block_total;
}

// ---------------------------------------------------------------------------
// CSR fill: csr[pos] = {src, dinv[src]}  (packed 8B write per edge)
// ---------------------------------------------------------------------------
__global__ void fill_kernel(const int* __restrict__ ei, long long E) {
    long long stride = (long long)gridDim.x * blockDim.x;
    for (long long e = (long long)blockIdx.x * blockDim.x + threadIdx.x;
         e < E; e += stride) {
        int s = ei[e];
        int d = ei[E + e];
        int pos = atomicAdd(&g_cursor[d], 1);
        g_csr[pos] = make_int2(s, __float_as_int(g_dinv[s]));
    }
}

// ---------------------------------------------------------------------------
// Aggregation + epilogue (fp16 gather, fp32 accumulate)  [R13 version]:
//   out[node] = relu( dinv[n]*(sum_e dinv[s] h[s] + dinv[n] h[n]) + b )
// One warp per node; 4 quarters x 8 lanes, LDG.128 per edge row.
// ---------------------------------------------------------------------------
template <typename OutT>
__global__ __launch_bounds__(256) void agg_kernel(
    const __half* __restrict__ h, const float* __restrict__ bias,
    OutT* __restrict__ outv)
{
    const int lane = threadIdx.x & 31;
    const int eq   = lane >> 3;     // edge slot within quad: 0..3
    const int fl   = lane & 7;      // feature octet: halves [fl*8, fl*8+8)
    const int gwarp = (blockIdx.x * blockDim.x + threadIdx.x) >> 5;
    const int nwarp = (gridDim.x * blockDim.x) >> 5;

    const float4 b0 = reinterpret_cast<const float4*>(bias)[fl * 2];
    const float4 b1 = reinterpret_cast<const float4*>(bias)[fl * 2 + 1];

    for (int node = gwarp; node < NNODES; node += nwarp) {
        const int beg = g_off[node];
        const int end = g_off[node + 1];
        const float di = g_dinv[node];

        float acc[8];
        if (eq == 0) {   // self-loop handled by quarter 0
            uint4 sv = *reinterpret_cast<const uint4*>(
                h + (size_t)node * FDIM + fl * 8);
            const __half2* hp = reinterpret_cast<const __half2*>(&sv);
#pragma unroll
            for (int p = 0; p < 4; p++) {
                float2 f = __half22float2(hp[p]);
                acc[2 * p]     = di * f.x;
                acc[2 * p + 1] = di * f.y;
            }
        } else {
#pragma unroll
            for (int p = 0; p < 8; p++) acc[p] = 0.f;
        }

        int base = beg;
        for (; base + 8 <= end; base += 8) {
            int2 e0 = g_csr[base + eq];
            int2 e1 = g_csr[base + 4 + eq];
            uint4 v0 = *reinterpret_cast<const uint4*>(
                h + (size_t)e0.x * FDIM + fl * 8);
            uint4 v1 = *reinterpret_cast<const uint4*>(
                h + (size_t)e1.x * FDIM + fl * 8);
            float w0 = __int_as_float(e0.y);
            float w1 = __int_as_float(e1.y);
            const __half2* p0 = reinterpret_cast<const __half2*>(&v0);
            const __half2* p1 = reinterpret_cast<const __half2*>(&v1);
#pragma unroll
            for (int p = 0; p < 4; p++) {
                float2 f0 = __half22float2(p0[p]);
                float2 f1 = __half22float2(p1[p]);
                acc[2 * p]     = fmaf(w0, f0.x, acc[2 * p]);
                acc[2 * p + 1] = fmaf(w0, f0.y, acc[2 * p + 1]);
                acc[2 * p]     = fmaf(w1, f1.x, acc[2 * p]);
                acc[2 * p + 1] = fmaf(w1, f1.y, acc[2 * p + 1]);
            }
        }
        for (; base < end; base += 4) {
            int idx = base + eq;
            int2 e0 = g_csr[idx < end ? idx : (end - 1)];
            float w0 = (idx < end) ? __int_as_float(e0.y) : 0.f;
            uint4 v0 = *reinterpret_cast<const uint4*>(
                h + (size_t)e0.x * FDIM + fl * 8);
            const __half2* p0 = reinterpret_cast<const __half2*>(&v0);
#pragma unroll
            for (int p = 0; p < 4; p++) {
                float2 f0 = __half22float2(p0[p]);
                acc[2 * p]     = fmaf(w0, f0.x, acc[2 * p]);
                acc[2 * p + 1] = fmaf(w0, f0.y, acc[2 * p + 1]);
            }
        }

#pragma unroll
        for (int p = 0; p < 8; p++) {
            acc[p] += __shfl_xor_sync(0xffffffffu, acc[p], 8);
            acc[p] += __shfl_xor_sync(0xffffffffu, acc[p], 16);
        }

        if (eq == 0) {   // lanes 0..7 write the 64-float row
            float r[8];
            r[0] = fmaxf(fmaf(acc[0], di, b0.x), 0.f);
            r[1] = fmaxf(fmaf(acc[1], di, b0.y), 0.f);
            r[2] = fmaxf(fmaf(acc[2], di, b0.z), 0.f);
            r[3] = fmaxf(fmaf(acc[3], di, b0.w), 0.f);
            r[4] = fmaxf(fmaf(acc[4], di, b1.x), 0.f);
            r[5] = fmaxf(fmaf(acc[5], di, b1.y), 0.f);
            r[6] = fmaxf(fmaf(acc[6], di, b1.z), 0.f);
            r[7] = fmaxf(fmaf(acc[7], di, b1.w), 0.f);
            if constexpr (sizeof(OutT) == 2) {   // fp16 activations
                union { __half2 hx[4]; uint4 u; } pk;
                pk.hx[0] = __floats2half2_rn(r[0], r[1]);
                pk.hx[1] = __floats2half2_rn(r[2], r[3]);
                pk.hx[2] = __floats2half2_rn(r[4], r[5]);
                pk.hx[3] = __floats2half2_rn(r[6], r[7]);
                *reinterpret_cast<uint4*>(
                    (__half*)outv + (size_t)node * FDIM + fl * 8) = pk.u;
            } else {                             // fp32 final output
                float4* o = reinterpret_cast<float4*>(
                    (float*)outv + (size_t)node * FDIM + fl * 8);
                o[0] = make_float4(r[0], r[1], r[2], r[3]);
                o[1] = make_float4(r[4], r[5], r[6], r[7]);
            }
        }
    }
}

// ---------------------------------------------------------------------------
// Tensor-core GEMM: C[n,64] = A[n,64] @ W[64,64]
// fp16 inputs (A converted on stage), fp32 accumulate, fp16 output.
// 256 threads / 256 rows per block; warp = 32 rows (2 m16 tiles).
// ---------------------------------------------------------------------------
#define GROWS 256

template <typename InT>
__global__ __launch_bounds__(256) void gemm_mma_kernel(
    const InT* __restrict__ A, const float* __restrict__ W,
    __half* __restrict__ C, int n_rows)
{
    __shared__ __half sA[GROWS * 72];    // 36864 B
    __shared__ __half sWT[64 * 72];      // 9216 B (WT[n][k] = W[k][n])

    const int tid  = threadIdx.x;
    const int row0 = blockIdx.x * GROWS;

    // stage WT (fp16, transposed)
    for (int idx = tid; idx < 4096; idx += 256) {
        int k = idx >> 6, n = idx & 63;
        sWT[n * 72 + k] = __float2half_rn(W[idx]);
    }

    // stage A (fp16): 256 rows x 32 half2
    for (int i = tid; i < GROWS * 32; i += 256) {
        int r   = i >> 5;
        int c2  = i & 31;
        int row = row0 + r;
        __half2 hv = __floats2half2_rn(0.f, 0.f);
        if (row < n_rows) {
            if constexpr (sizeof(InT) == 2) {
                hv = *reinterpret_cast<const __half2*>(
                    reinterpret_cast<const __half*>(A)
                    + (size_t)row * FDIM + c2 * 2);
            } else {
                float2 f = *reinterpret_cast<const float2*>(
                    reinterpret_cast<const float*>(A)
                    + (size_t)row * FDIM + c2 * 2);
                hv = __floats2half2_rn(f.x, f.y);
            }
        }
        *reinterpret_cast<__half2*>(&sA[r * 72 + c2 * 2]) = hv;
    }
    __syncthreads();

    const int lane = tid & 31;
    const int warp = tid >> 5;
    const int r    = lane >> 2;     // 0..7
    const int cq   = lane & 3;      // 0..3
    const int wrow = warp * 32;

    uint32_t afr[2][4][4];
#pragma unroll
    for (int mt = 0; mt < 2; mt++) {
        int rm = wrow + mt * 16;
#pragma unroll
        for (int kc = 0; kc < 4; kc++) {
            int kb = kc * 16;
            afr[mt][kc][0] = *reinterpret_cast<const uint32_t*>(
                &sA[(rm + r) * 72 + kb + cq * 2]);
            afr[mt][kc][1] = *reinterpret_cast<const uint32_t*>(
                &sA[(rm + r + 8) * 72 + kb + cq * 2]);
            afr[mt][kc][2] = *reinterpret_cast<const uint32_t*>(
                &sA[(rm + r) * 72 + kb + cq * 2 + 8]);
            afr[mt][kc][3] = *reinterpret_cast<const uint32_t*>(
                &sA[(rm + r + 8) * 72 + kb + cq * 2 + 8]);
        }
    }

#pragma unroll
    for (int nt = 0; nt < 8; nt++) {
        int nb = nt * 8;
        float acc[2][4] = {{0.f, 0.f, 0.f, 0.f}, {0.f, 0.f, 0.f, 0.f}};
#pragma unroll
        for (int kc = 0; kc < 4; kc++) {
            int kb = kc * 16;
            uint32_t b0 = *reinterpret_cast<const uint32_t*>(
                &sWT[(nb + r) * 72 + kb + cq * 2]);
            uint32_t b1 = *reinterpret_cast<const uint32_t*>(
                &sWT[(nb + r) * 72 + kb + cq * 2 + 8]);
#pragma unroll
            for (int mt = 0; mt < 2; mt++) {
                asm volatile(
                    "mma.sync.aligned.m16n8k16.row.col.f32.f16.f16.f32 "
                    "{%0,%1,%2,%3}, {%4,%5,%6,%7}, {%8,%9}, {%0,%1,%2,%3};"
                    : "+f"(acc[mt][0]), "+f"(acc[mt][1]),
                      "+f"(acc[mt][2]), "+f"(acc[mt][3])
                    : "r"(afr[mt][kc][0]), "r"(afr[mt][kc][1]),
                      "r"(afr[mt][kc][2]), "r"(afr[mt][kc][3]),
                      "r"(b0), "r"(b1));
            }
        }
#pragma unroll
        for (int mt = 0; mt < 2; mt++) {
            int row = row0 + wrow + mt * 16 + r;
            int col = nb + cq * 2;
            if (row < n_rows)
                *reinterpret_cast<__half2*>(C + (size_t)row * FDIM + col) =
                    __floats2half2_rn(acc[mt][0], acc[mt][1]);
            if (row + 8 < n_rows)
                *reinterpret_cast<__half2*>(C + (size_t)(row + 8) * FDIM + col) =
                    __floats2half2_rn(acc[mt][2], acc[mt][3]);
        }
    }
}

// ---------------------------------------------------------------------------
extern "C" void kernel_launch(void* const* d_in, const int* in_sizes, int n_in,
                              void* d_out, int out_size)
{
    const float* x  = (const float*)d_in[0];
    const int*   ei = (const int*)d_in[1];     // int32 (JAX x64 disabled)
    const float* W1 = (const float*)d_in[2];
    const float* b1 = (const float*)d_in[3];
    const float* W2 = (const float*)d_in[4];
    const float* b2 = (const float*)d_in[5];
    float* out = (float*)d_out;

    const long long E = (long long)in_sizes[1] / 2;

    __half* g_hh_ptr;   cudaGetSymbolAddress((void**)&g_hh_ptr,   g_hh);
    __half* g_ah_ptr;   cudaGetSymbolAddress((void**)&g_ah_ptr,   g_ah);
    int*    g_degi_ptr; cudaGetSymbolAddress((void**)&g_degi_ptr, g_degi);
    int*    g_flag_ptr; cudaGetSymbolAddress((void**)&g_flag_ptr, g_flagz);

    const int SMS = 148;
    dim3 blk(256);

    const int gemm_grid = (NNODES + GROWS - 1) / GROWS;   // 391
    const int agg_grid  = SMS * 24;

    // ---- CSR build ----
    cudaMemsetAsync(g_degi_ptr, 0, NNODES * sizeof(int));
    cudaMemsetAsync(g_flag_ptr, 0, NSCANBLK * sizeof(int));
    hist_kernel<<<SMS * 8, blk>>>(ei, E);
    scan_kernel<<<NSCANBLK, SCAN_BLK>>>();   // scan + dinv, single launch
    fill_kernel<<<SMS * 8, blk>>>(ei, E);

    // ---- layer 1 ----
    gemm_mma_kernel<float><<<gemm_grid, blk>>>(x, W1, g_hh_ptr, NNODES);
    agg_kernel<__half><<<agg_grid, blk>>>(g_hh_ptr, b1, g_ah_ptr);

    // ---- layer 2 ----
    gemm_mma_kernel<__half><<<gemm_grid, blk>>>(g_ah_ptr, W2, g_hh_ptr, NNODES);
    agg_kernel<float><<<agg_grid, blk>>>(g_hh_ptr, b2, out);
}

// round 16
// speedup vs baseline: 1.1628x; 1.0047x over previous
#include <cuda_runtime.h>
#include <cuda_fp16.h>
#include <stdint.h>

#define NNODES 100000
#define FDIM   64
#define EMAX   2000000   // reference uses E=1.6M; headroom

#define SCAN_BLK   1024
#define NSCANBLK   ((NNODES + SCAN_BLK - 1) / SCAN_BLK)   // 98

// ---------------------------------------------------------------------------
// Static device scratch (no allocation allowed anywhere)
// ---------------------------------------------------------------------------
__device__ __align__(16) __half g_hh[(size_t)NNODES * FDIM];  // 12.8 MB (h, fp16)
__device__ __align__(16) __half g_ah[(size_t)NNODES * FDIM];  // 12.8 MB (act, fp16)
__device__ float g_dinv[NNODES];
__device__ int   g_degi[NNODES];
__device__ int   g_off[NNODES + 1];
__device__ int   g_cursor[NNODES];
__device__ int   g_bsum[NSCANBLK];
__device__ int   g_bpre[NSCANBLK];
__device__ __align__(16) int2 g_csr[EMAX];  // {src, bitcast(dinv[src])} 16 MB

// ---------------------------------------------------------------------------
// histogram of in-edges (int atomics, exact). edge_index int32, [2, E].
// ---------------------------------------------------------------------------
__global__ void hist_kernel(const int* __restrict__ ei, long long E) {
    long long stride = (long long)gridDim.x * blockDim.x;
    for (long long e = (long long)blockIdx.x * blockDim.x + threadIdx.x;
         e < E; e += stride)
        atomicAdd(&g_degi[ei[E + e]], 1);
}

// ---------------------------------------------------------------------------
// Multi-block exclusive scan of g_degi -> g_off (+ cursor copy). 3 phases.
// Phase 1 also computes dinv (reads degi anyway).
// ---------------------------------------------------------------------------
__global__ __launch_bounds__(SCAN_BLK) void scan_reduce_kernel() {
    __shared__ int sh[SCAN_BLK / 32];
    int i = blockIdx.x * SCAN_BLK + threadIdx.x;
    int v = 0;
    if (i < NNODES) {
        v = g_degi[i];
        g_dinv[i] = rsqrtf((float)v + 1.0f);   // fused dinv
    }
    int r = v;
#pragma unroll
    for (int o = 16; o > 0; o >>= 1)
        r += __shfl_down_sync(0xffffffffu, r, o);
    if ((threadIdx.x & 31) == 0) sh[threadIdx.x >> 5] = r;
    __syncthreads();
    if (threadIdx.x < 32) {
        int w = (threadIdx.x < SCAN_BLK / 32) ? sh[threadIdx.x] : 0;
#pragma unroll
        for (int o = 16; o > 0; o >>= 1)
            w += __shfl_down_sync(0xffffffffu, w, o);
        if (threadIdx.x == 0) g_bsum[blockIdx.x] = w;
    }
}

__global__ __launch_bounds__(128) void scan_bsum_kernel() {
    __shared__ int sh[128];
    int tid = threadIdx.x;
    int v = (tid < NSCANBLK) ? g_bsum[tid] : 0;
    sh[tid] = v;
    __syncthreads();
    for (int o = 1; o < 128; o <<= 1) {
        int t = (tid >= o) ? sh[tid - o] : 0;
        __syncthreads();
        sh[tid] += t;
        __syncthreads();
    }
    if (tid < NSCANBLK) g_bpre[tid] = sh[tid] - v;   // exclusive
    if (tid == 127) g_off[NNODES] = sh[127];         // total
}

__global__ __launch_bounds__(SCAN_BLK) void scan_write_kernel() {
    __shared__ int sh[SCAN_BLK];
    int tid = threadIdx.x;
    int i = blockIdx.x * SCAN_BLK + tid;
    int v = (i < NNODES) ? g_degi[i] : 0;
    sh[tid] = v;
    __syncthreads();
    for (int o = 1; o < SCAN_BLK; o <<= 1) {
        int t = (tid >= o) ? sh[tid - o] : 0;
        __syncthreads();
        sh[tid] += t;
        __syncthreads();
    }
    if (i < NNODES) {
        int off = g_bpre[blockIdx.x] + sh[tid] - v;  // exclusive
        g_off[i]    = off;
        g_cursor[i] = off;
    }
}

// ---------------------------------------------------------------------------
// CSR fill: csr[pos] = {src, dinv[src]}  (packed 8B write per edge)
// ---------------------------------------------------------------------------
__global__ void fill_kernel(const int* __restrict__ ei, long long E) {
    long long stride = (long long)gridDim.x * blockDim.x;
    for (long long e = (long long)blockIdx.x * blockDim.x + threadIdx.x;
         e < E; e += stride) {
        int s = ei[e];
        int d = ei[E + e];
        int pos = atomicAdd(&g_cursor[d], 1);
        g_csr[pos] = make_int2(s, __float_as_int(g_dinv[s]));
    }
}

// ---------------------------------------------------------------------------
// Aggregation + epilogue (fp16 gather, fp32 accumulate):
//   out[node] = relu( dinv[n]*(sum_e dinv[s] h[s] + dinv[n] h[n]) + b )
// One warp per node; 4 quarters x 8 lanes, LDG.128 per edge row.
// MAIN LOOP = 16 edges/iter: 4 CSR reads + 4 independent row loads issue
// back-to-back -> ONE exposed L2 latency for the typical deg~16 node.
// ---------------------------------------------------------------------------
template <typename OutT>
__global__ __launch_bounds__(256) void agg_kernel(
    const __half* __restrict__ h, const float* __restrict__ bias,
    OutT* __restrict__ outv)
{
    const int lane = threadIdx.x & 31;
    const int eq   = lane >> 3;     // edge slot within quad: 0..3
    const int fl   = lane & 7;      // feature octet: halves [fl*8, fl*8+8)
    const int gwarp = (blockIdx.x * blockDim.x + threadIdx.x) >> 5;
    const int nwarp = (gridDim.x * blockDim.x) >> 5;

    const float4 b0 = reinterpret_cast<const float4*>(bias)[fl * 2];
    const float4 b1 = reinterpret_cast<const float4*>(bias)[fl * 2 + 1];

    for (int node = gwarp; node < NNODES; node += nwarp) {
        const int beg = g_off[node];
        const int end = g_off[node + 1];
        const float di = g_dinv[node];

        float acc[8];
        if (eq == 0) {   // self-loop handled by quarter 0
            uint4 sv = *reinterpret_cast<const uint4*>(
                h + (size_t)node * FDIM + fl * 8);
            const __half2* hp = reinterpret_cast<const __half2*>(&sv);
#pragma unroll
            for (int p = 0; p < 4; p++) {
                float2 f = __half22float2(hp[p]);
                acc[2 * p]     = di * f.x;
                acc[2 * p + 1] = di * f.y;
            }
        } else {
#pragma unroll
            for (int p = 0; p < 8; p++) acc[p] = 0.f;
        }

        int base = beg;
        // ---- 16 edges per iteration: 4 independent LDG.128 chains ----
        for (; base + 16 <= end; base += 16) {
            int2 e0 = g_csr[base + eq];
            int2 e1 = g_csr[base + 4 + eq];
            int2 e2 = g_csr[base + 8 + eq];
            int2 e3 = g_csr[base + 12 + eq];
            uint4 v0 = *reinterpret_cast<const uint4*>(
                h + (size_t)e0.x * FDIM + fl * 8);
            uint4 v1 = *reinterpret_cast<const uint4*>(
                h + (size_t)e1.x * FDIM + fl * 8);
            uint4 v2 = *reinterpret_cast<const uint4*>(
                h + (size_t)e2.x * FDIM + fl * 8);
            uint4 v3 = *reinterpret_cast<const uint4*>(
                h + (size_t)e3.x * FDIM + fl * 8);
            float w0 = __int_as_float(e0.y);
            float w1 = __int_as_float(e1.y);
            float w2 = __int_as_float(e2.y);
            float w3 = __int_as_float(e3.y);
            const __half2* p0 = reinterpret_cast<const __half2*>(&v0);
            const __half2* p1 = reinterpret_cast<const __half2*>(&v1);
            const __half2* p2 = reinterpret_cast<const __half2*>(&v2);
            const __half2* p3 = reinterpret_cast<const __half2*>(&v3);
#pragma unroll
            for (int p = 0; p < 4; p++) {
                float2 f0 = __half22float2(p0[p]);
                float2 f1 = __half22float2(p1[p]);
                float2 f2 = __half22float2(p2[p]);
                float2 f3 = __half22float2(p3[p]);
                acc[2 * p]     = fmaf(w0, f0.x, acc[2 * p]);
                acc[2 * p + 1] = fmaf(w0, f0.y, acc[2 * p + 1]);
                acc[2 * p]     = fmaf(w1, f1.x, acc[2 * p]);
                acc[2 * p + 1] = fmaf(w1, f1.y, acc[2 * p + 1]);
                acc[2 * p]     = fmaf(w2, f2.x, acc[2 * p]);
                acc[2 * p + 1] = fmaf(w2, f2.y, acc[2 * p + 1]);
                acc[2 * p]     = fmaf(w3, f3.x, acc[2 * p]);
                acc[2 * p + 1] = fmaf(w3, f3.y, acc[2 * p + 1]);
            }
        }
        // ---- remainder: up to 15 edges, 4 at a time, zero-padded ----
        for (; base < end; base += 4) {
            int idx = base + eq;
            int2 e0 = g_csr[idx < end ? idx : (end - 1)];
            float w0 = (idx < end) ? __int_as_float(e0.y) : 0.f;
            uint4 v0 = *reinterpret_cast<const uint4*>(
                h + (size_t)e0.x * FDIM + fl * 8);
            const __half2* p0 = reinterpret_cast<const __half2*>(&v0);
#pragma unroll
            for (int p = 0; p < 4; p++) {
                float2 f0 = __half22float2(p0[p]);
                acc[2 * p]     = fmaf(w0, f0.x, acc[2 * p]);
                acc[2 * p + 1] = fmaf(w0, f0.y, acc[2 * p + 1]);
            }
        }

#pragma unroll
        for (int p = 0; p < 8; p++) {
            acc[p] += __shfl_xor_sync(0xffffffffu, acc[p], 8);
            acc[p] += __shfl_xor_sync(0xffffffffu, acc[p], 16);
        }

        if (eq == 0) {   // lanes 0..7 write the 64-float row
            float r[8];
            r[0] = fmaxf(fmaf(acc[0], di, b0.x), 0.f);
            r[1] = fmaxf(fmaf(acc[1], di, b0.y), 0.f);
            r[2] = fmaxf(fmaf(acc[2], di, b0.z), 0.f);
            r[3] = fmaxf(fmaf(acc[3], di, b0.w), 0.f);
            r[4] = fmaxf(fmaf(acc[4], di, b1.x), 0.f);
            r[5] = fmaxf(fmaf(acc[5], di, b1.y), 0.f);
            r[6] = fmaxf(fmaf(acc[6], di, b1.z), 0.f);
            r[7] = fmaxf(fmaf(acc[7], di, b1.w), 0.f);
            if constexpr (sizeof(OutT) == 2) {   // fp16 activations
                union { __half2 hx[4]; uint4 u; } pk;
                pk.hx[0] = __floats2half2_rn(r[0], r[1]);
                pk.hx[1] = __floats2half2_rn(r[2], r[3]);
                pk.hx[2] = __floats2half2_rn(r[4], r[5]);
                pk.hx[3] = __floats2half2_rn(r[6], r[7]);
                *reinterpret_cast<uint4*>(
                    (__half*)outv + (size_t)node * FDIM + fl * 8) = pk.u;
            } else {                             // fp32 final output
                float4* o = reinterpret_cast<float4*>(
                    (float*)outv + (size_t)node * FDIM + fl * 8);
                o[0] = make_float4(r[0], r[1], r[2], r[3]);
                o[1] = make_float4(r[4], r[5], r[6], r[7]);
            }
        }
    }
}

// ---------------------------------------------------------------------------
// Tensor-core GEMM: C[n,64] = A[n,64] @ W[64,64]
// fp16 inputs (A converted on stage), fp32 accumulate, fp16 output.
// 256 threads / 256 rows per block; warp = 32 rows (2 m16 tiles).
// ---------------------------------------------------------------------------
#define GROWS 256

template <typename InT>
__global__ __launch_bounds__(256) void gemm_mma_kernel(
    const InT* __restrict__ A, const float* __restrict__ W,
    __half* __restrict__ C, int n_rows)
{
    __shared__ __half sA[GROWS * 72];    // 36864 B
    __shared__ __half sWT[64 * 72];      // 9216 B (WT[n][k] = W[k][n])

    const int tid  = threadIdx.x;
    const int row0 = blockIdx.x * GROWS;

    // stage WT (fp16, transposed)
    for (int idx = tid; idx < 4096; idx += 256) {
        int k = idx >> 6, n = idx & 63;
        sWT[n * 72 + k] = __float2half_rn(W[idx]);
    }

    // stage A (fp16): 256 rows x 32 half2
    for (int i = tid; i < GROWS * 32; i += 256) {
        int r   = i >> 5;
        int c2  = i & 31;
        int row = row0 + r;
        __half2 hv = __floats2half2_rn(0.f, 0.f);
        if (row < n_rows) {
            if constexpr (sizeof(InT) == 2) {
                hv = *reinterpret_cast<const __half2*>(
                    reinterpret_cast<const __half*>(A)
                    + (size_t)row * FDIM + c2 * 2);
            } else {
                float2 f = *reinterpret_cast<const float2*>(
                    reinterpret_cast<const float*>(A)
                    + (size_t)row * FDIM + c2 * 2);
                hv = __floats2half2_rn(f.x, f.y);
            }
        }
        *reinterpret_cast<__half2*>(&sA[r * 72 + c2 * 2]) = hv;
    }
    __syncthreads();

    const int lane = tid & 31;
    const int warp = tid >> 5;
    const int r    = lane >> 2;     // 0..7
    const int cq   = lane & 3;      // 0..3
    const int wrow = warp * 32;

    uint32_t afr[2][4][4];
#pragma unroll
    for (int mt = 0; mt < 2; mt++) {
        int rm = wrow + mt * 16;
#pragma unroll
        for (int kc = 0; kc < 4; kc++) {
            int kb = kc * 16;
            afr[mt][kc][0] = *reinterpret_cast<const uint32_t*>(
                &sA[(rm + r) * 72 + kb + cq * 2]);
            afr[mt][kc][1] = *reinterpret_cast<const uint32_t*>(
                &sA[(rm + r + 8) * 72 + kb + cq * 2]);
            afr[mt][kc][2] = *reinterpret_cast<const uint32_t*>(
                &sA[(rm + r) * 72 + kb + cq * 2 + 8]);
            afr[mt][kc][3] = *reinterpret_cast<const uint32_t*>(
                &sA[(rm + r + 8) * 72 + kb + cq * 2 + 8]);
        }
    }

#pragma unroll
    for (int nt = 0; nt < 8; nt++) {
        int nb = nt * 8;
        float acc[2][4] = {{0.f, 0.f, 0.f, 0.f}, {0.f, 0.f, 0.f, 0.f}};
#pragma unroll
        for (int kc = 0; kc < 4; kc++) {
            int kb = kc * 16;
            uint32_t b0 = *reinterpret_cast<const uint32_t*>(
                &sWT[(nb + r) * 72 + kb + cq * 2]);
            uint32_t b1 = *reinterpret_cast<const uint32_t*>(
                &sWT[(nb + r) * 72 + kb + cq * 2 + 8]);
#pragma unroll
            for (int mt = 0; mt < 2; mt++) {
                asm volatile(
                    "mma.sync.aligned.m16n8k16.row.col.f32.f16.f16.f32 "
                    "{%0,%1,%2,%3}, {%4,%5,%6,%7}, {%8,%9}, {%0,%1,%2,%3};"
                    : "+f"(acc[mt][0]), "+f"(acc[mt][1]),
                      "+f"(acc[mt][2]), "+f"(acc[mt][3])
                    : "r"(afr[mt][kc][0]), "r"(afr[mt][kc][1]),
                      "r"(afr[mt][kc][2]), "r"(afr[mt][kc][3]),
                      "r"(b0), "r"(b1));
            }
        }
#pragma unroll
        for (int mt = 0; mt < 2; mt++) {
            int row = row0 + wrow + mt * 16 + r;
            int col = nb + cq * 2;
            if (row < n_rows)
                *reinterpret_cast<__half2*>(C + (size_t)row * FDIM + col) =
                    __floats2half2_rn(acc[mt][0], acc[mt][1]);
            if (row + 8 < n_rows)
                *reinterpret_cast<__half2*>(C + (size_t)(row + 8) * FDIM + col) =
                    __floats2half2_rn(acc[mt][2], acc[mt][3]);
        }
    }
}

// ---------------------------------------------------------------------------
extern "C" void kernel_launch(void* const* d_in, const int* in_sizes, int n_in,
                              void* d_out, int out_size)
{
    const float* x  = (const float*)d_in[0];
    const int*   ei = (const int*)d_in[1];     // int32 (JAX x64 disabled)
    const float* W1 = (const float*)d_in[2];
    const float* b1 = (const float*)d_in[3];
    const float* W2 = (const float*)d_in[4];
    const float* b2 = (const float*)d_in[5];
    float* out = (float*)d_out;

    const long long E = (long long)in_sizes[1] / 2;

    __half* g_hh_ptr;   cudaGetSymbolAddress((void**)&g_hh_ptr,   g_hh);
    __half* g_ah_ptr;   cudaGetSymbolAddress((void**)&g_ah_ptr,   g_ah);
    int*    g_degi_ptr; cudaGetSymbolAddress((void**)&g_degi_ptr, g_degi);

    const int SMS = 148;
    dim3 blk(256);

    const int gemm_grid = (NNODES + GROWS - 1) / GROWS;   // 391
    const int agg_grid  = SMS * 24;

    // ---- CSR build ----
    cudaMemsetAsync(g_degi_ptr, 0, NNODES * sizeof(int));
    hist_kernel<<<SMS * 8, blk>>>(ei, E);
    scan_reduce_kernel<<<NSCANBLK, SCAN_BLK>>>();   // also computes dinv
    scan_bsum_kernel<<<1, 128>>>();
    scan_write_kernel<<<NSCANBLK, SCAN_BLK>>>();
    fill_kernel<<<SMS * 8, blk>>>(ei, E);

    // ---- layer 1 ----
    gemm_mma_kernel<float><<<gemm_grid, blk>>>(x, W1, g_hh_ptr, NNODES);
    agg_kernel<__half><<<agg_grid, blk>>>(g_hh_ptr, b1, g_ah_ptr);

    // ---- layer 2 ----
    gemm_mma_kernel<__half><<<gemm_grid, blk>>>(g_ah_ptr, W2, g_hh_ptr, NNODES);
    agg_kernel<float><<<agg_grid, blk>>>(g_hh_ptr, b2, out);
}

// round 17
// speedup vs baseline: 1.1648x; 1.0016x over previous
#include <cuda_runtime.h>
#include <cuda_fp16.h>
#include <stdint.h>

#define NNODES 100000
#define FDIM   64
#define EMAX   2000000   // reference uses E=1.6M; headroom

#define SCAN_BLK   1024
#define NSCANBLK   ((NNODES + SCAN_BLK - 1) / SCAN_BLK)   // 98

// ---------------------------------------------------------------------------
// Static device scratch (no allocation allowed anywhere)
// ---------------------------------------------------------------------------
__device__ __align__(16) __half g_hh[(size_t)NNODES * FDIM];  // 12.8 MB (h, fp16)
__device__ __align__(16) __half g_ah[(size_t)NNODES * FDIM];  // 12.8 MB (act, fp16)
__device__ float g_dinv[NNODES];
__device__ int   g_degi[NNODES];
__device__ int   g_off[NNODES + 1];
__device__ int   g_cursor[NNODES];
__device__ int   g_bsum[NSCANBLK];
__device__ int   g_bpre[NSCANBLK];
__device__ __align__(16) int2 g_csr[EMAX];  // {src, bitcast(dinv[src])} 16 MB

// ---------------------------------------------------------------------------
// histogram of in-edges (int atomics, exact). edge_index int32, [2, E].
// ---------------------------------------------------------------------------
__global__ void hist_kernel(const int* __restrict__ ei, long long E) {
    long long stride = (long long)gridDim.x * blockDim.x;
    for (long long e = (long long)blockIdx.x * blockDim.x + threadIdx.x;
         e < E; e += stride)
        atomicAdd(&g_degi[ei[E + e]], 1);
}

// ---------------------------------------------------------------------------
// Multi-block exclusive scan of g_degi -> g_off (+ cursor copy). 3 phases.
// Phase 1 also computes dinv (reads degi anyway).
// ---------------------------------------------------------------------------
__global__ __launch_bounds__(SCAN_BLK) void scan_reduce_kernel() {
    __shared__ int sh[SCAN_BLK / 32];
    int i = blockIdx.x * SCAN_BLK + threadIdx.x;
    int v = 0;
    if (i < NNODES) {
        v = g_degi[i];
        g_dinv[i] = rsqrtf((float)v + 1.0f);   // fused dinv
    }
    int r = v;
#pragma unroll
    for (int o = 16; o > 0; o >>= 1)
        r += __shfl_down_sync(0xffffffffu, r, o);
    if ((threadIdx.x & 31) == 0) sh[threadIdx.x >> 5] = r;
    __syncthreads();
    if (threadIdx.x < 32) {
        int w = (threadIdx.x < SCAN_BLK / 32) ? sh[threadIdx.x] : 0;
#pragma unroll
        for (int o = 16; o > 0; o >>= 1)
            w += __shfl_down_sync(0xffffffffu, w, o);
        if (threadIdx.x == 0) g_bsum[blockIdx.x] = w;
    }
}

__global__ __launch_bounds__(128) void scan_bsum_kernel() {
    __shared__ int sh[128];
    int tid = threadIdx.x;
    int v = (tid < NSCANBLK) ? g_bsum[tid] : 0;
    sh[tid] = v;
    __syncthreads();
    for (int o = 1; o < 128; o <<= 1) {
        int t = (tid >= o) ? sh[tid - o] : 0;
        __syncthreads();
        sh[tid] += t;
        __syncthreads();
    }
    if (tid < NSCANBLK) g_bpre[tid] = sh[tid] - v;   // exclusive
    if (tid == 127) g_off[NNODES] = sh[127];         // total
}

__global__ __launch_bounds__(SCAN_BLK) void scan_write_kernel() {
    __shared__ int sh[SCAN_BLK];
    int tid = threadIdx.x;
    int i = blockIdx.x * SCAN_BLK + tid;
    int v = (i < NNODES) ? g_degi[i] : 0;
    sh[tid] = v;
    __syncthreads();
    for (int o = 1; o < SCAN_BLK; o <<= 1) {
        int t = (tid >= o) ? sh[tid - o] : 0;
        __syncthreads();
        sh[tid] += t;
        __syncthreads();
    }
    if (i < NNODES) {
        int off = g_bpre[blockIdx.x] + sh[tid] - v;  // exclusive
        g_off[i]    = off;
        g_cursor[i] = off;
    }
}

// ---------------------------------------------------------------------------
// CSR fill: csr[pos] = {src, dinv[src]}  (packed 8B write per edge)
// ---------------------------------------------------------------------------
__global__ void fill_kernel(const int* __restrict__ ei, long long E) {
    long long stride = (long long)gridDim.x * blockDim.x;
    for (long long e = (long long)blockIdx.x * blockDim.x + threadIdx.x;
         e < E; e += stride) {
        int s = ei[e];
        int d = ei[E + e];
        int pos = atomicAdd(&g_cursor[d], 1);
        g_csr[pos] = make_int2(s, __float_as_int(g_dinv[s]));
    }
}

// ---------------------------------------------------------------------------
// Aggregation + epilogue (fp16 gather, fp32 accumulate)  [R13 version]:
//   out[node] = relu( dinv[n]*(sum_e dinv[s] h[s] + dinv[n] h[n]) + b )
// One warp per node; 4 quarters x 8 lanes, LDG.128 per edge row.
// ---------------------------------------------------------------------------
template <typename OutT>
__global__ __launch_bounds__(256) void agg_kernel(
    const __half* __restrict__ h, const float* __restrict__ bias,
    OutT* __restrict__ outv)
{
    const int lane = threadIdx.x & 31;
    const int eq   = lane >> 3;     // edge slot within quad: 0..3
    const int fl   = lane & 7;      // feature octet: halves [fl*8, fl*8+8)
    const int gwarp = (blockIdx.x * blockDim.x + threadIdx.x) >> 5;
    const int nwarp = (gridDim.x * blockDim.x) >> 5;

    const float4 b0 = reinterpret_cast<const float4*>(bias)[fl * 2];
    const float4 b1 = reinterpret_cast<const float4*>(bias)[fl * 2 + 1];

    for (int node = gwarp; node < NNODES; node += nwarp) {
        const int beg = g_off[node];
        const int end = g_off[node + 1];
        const float di = g_dinv[node];

        float acc[8];
        if (eq == 0) {   // self-loop handled by quarter 0
            uint4 sv = *reinterpret_cast<const uint4*>(
                h + (size_t)node * FDIM + fl * 8);
            const __half2* hp = reinterpret_cast<const __half2*>(&sv);
#pragma unroll
            for (int p = 0; p < 4; p++) {
                float2 f = __half22float2(hp[p]);
                acc[2 * p]     = di * f.x;
                acc[2 * p + 1] = di * f.y;
            }
        } else {
#pragma unroll
            for (int p = 0; p < 8; p++) acc[p] = 0.f;
        }

        int base = beg;
        for (; base + 8 <= end; base += 8) {
            int2 e0 = g_csr[base + eq];
            int2 e1 = g_csr[base + 4 + eq];
            uint4 v0 = *reinterpret_cast<const uint4*>(
                h + (size_t)e0.x * FDIM + fl * 8);
            uint4 v1 = *reinterpret_cast<const uint4*>(
                h + (size_t)e1.x * FDIM + fl * 8);
            float w0 = __int_as_float(e0.y);
            float w1 = __int_as_float(e1.y);
            const __half2* p0 = reinterpret_cast<const __half2*>(&v0);
            const __half2* p1 = reinterpret_cast<const __half2*>(&v1);
#pragma unroll
            for (int p = 0; p < 4; p++) {
                float2 f0 = __half22float2(p0[p]);
                float2 f1 = __half22float2(p1[p]);
                acc[2 * p]     = fmaf(w0, f0.x, acc[2 * p]);
                acc[2 * p + 1] = fmaf(w0, f0.y, acc[2 * p + 1]);
                acc[2 * p]     = fmaf(w1, f1.x, acc[2 * p]);
                acc[2 * p + 1] = fmaf(w1, f1.y, acc[2 * p + 1]);
            }
        }
        for (; base < end; base += 4) {
            int idx = base + eq;
            int2 e0 = g_csr[idx < end ? idx : (end - 1)];
            float w0 = (idx < end) ? __int_as_float(e0.y) : 0.f;
            uint4 v0 = *reinterpret_cast<const uint4*>(
                h + (size_t)e0.x * FDIM + fl * 8);
            const __half2* p0 = reinterpret_cast<const __half2*>(&v0);
#pragma unroll
            for (int p = 0; p < 4; p++) {
                float2 f0 = __half22float2(p0[p]);
                acc[2 * p]     = fmaf(w0, f0.x, acc[2 * p]);
                acc[2 * p + 1] = fmaf(w0, f0.y, acc[2 * p + 1]);
            }
        }

#pragma unroll
        for (int p = 0; p < 8; p++) {
            acc[p] += __shfl_xor_sync(0xffffffffu, acc[p], 8);
            acc[p] += __shfl_xor_sync(0xffffffffu, acc[p], 16);
        }

        if (eq == 0) {   // lanes 0..7 write the 64-float row
            float r[8];
            r[0] = fmaxf(fmaf(acc[0], di, b0.x), 0.f);
            r[1] = fmaxf(fmaf(acc[1], di, b0.y), 0.f);
            r[2] = fmaxf(fmaf(acc[2], di, b0.z), 0.f);
            r[3] = fmaxf(fmaf(acc[3], di, b0.w), 0.f);
            r[4] = fmaxf(fmaf(acc[4], di, b1.x), 0.f);
            r[5] = fmaxf(fmaf(acc[5], di, b1.y), 0.f);
            r[6] = fmaxf(fmaf(acc[6], di, b1.z), 0.f);
            r[7] = fmaxf(fmaf(acc[7], di, b1.w), 0.f);
            if constexpr (sizeof(OutT) == 2) {   // fp16 activations
                union { __half2 hx[4]; uint4 u; } pk;
                pk.hx[0] = __floats2half2_rn(r[0], r[1]);
                pk.hx[1] = __floats2half2_rn(r[2], r[3]);
                pk.hx[2] = __floats2half2_rn(r[4], r[5]);
                pk.hx[3] = __floats2half2_rn(r[6], r[7]);
                *reinterpret_cast<uint4*>(
                    (__half*)outv + (size_t)node * FDIM + fl * 8) = pk.u;
            } else {                             // fp32 final output
                float4* o = reinterpret_cast<float4*>(
                    (float*)outv + (size_t)node * FDIM + fl * 8);
                o[0] = make_float4(r[0], r[1], r[2], r[3]);
                o[1] = make_float4(r[4], r[5], r[6], r[7]);
            }
        }
    }
}

// ---------------------------------------------------------------------------
// Tensor-core GEMM: C[n,64] = A[n,64] @ W[64,64]
// fp16 inputs (A converted on stage), fp32 accumulate, fp16 output.
// GROWS=128 / 256 threads: warp = 16 rows (ONE m16 tile); smem 27.6 KB ->
// 6-8 blocks/SM co-resident, staging latency hidden by neighbor compute.
// ---------------------------------------------------------------------------
#define GROWS 128

template <typename InT>
__global__ __launch_bounds__(256) void gemm_mma_kernel(
    const InT* __restrict__ A, const float* __restrict__ W,
    __half* __restrict__ C, int n_rows)
{
    __shared__ __half sA[GROWS * 72];    // 18432 B
    __shared__ __half sWT[64 * 72];      // 9216 B (WT[n][k] = W[k][n])

    const int tid  = threadIdx.x;
    const int row0 = blockIdx.x * GROWS;

    // stage WT (fp16, transposed)
    for (int idx = tid; idx < 4096; idx += 256) {
        int k = idx >> 6, n = idx & 63;
        sWT[n * 72 + k] = __float2half_rn(W[idx]);
    }

    // stage A (fp16): 128 rows x 32 half2
    for (int i = tid; i < GROWS * 32; i += 256) {
        int r   = i >> 5;
        int c2  = i & 31;
        int row = row0 + r;
        __half2 hv = __floats2half2_rn(0.f, 0.f);
        if (row < n_rows) {
            if constexpr (sizeof(InT) == 2) {
                hv = *reinterpret_cast<const __half2*>(
                    reinterpret_cast<const __half*>(A)
                    + (size_t)row * FDIM + c2 * 2);
            } else {
                float2 f = *reinterpret_cast<const float2*>(
                    reinterpret_cast<const float*>(A)
                    + (size_t)row * FDIM + c2 * 2);
                hv = __floats2half2_rn(f.x, f.y);
            }
        }
        *reinterpret_cast<__half2*>(&sA[r * 72 + c2 * 2]) = hv;
    }
    __syncthreads();

    const int lane = tid & 31;
    const int warp = tid >> 5;
    const int r    = lane >> 2;     // 0..7
    const int cq   = lane & 3;      // 0..3
    const int wrow = warp * 16;     // one m16 tile per warp

    // A fragments: 4 k-chunks x 4 b32
    uint32_t afr[4][4];
#pragma unroll
    for (int kc = 0; kc < 4; kc++) {
        int kb = kc * 16;
        afr[kc][0] = *reinterpret_cast<const uint32_t*>(
            &sA[(wrow + r) * 72 + kb + cq * 2]);
        afr[kc][1] = *reinterpret_cast<const uint32_t*>(
            &sA[(wrow + r + 8) * 72 + kb + cq * 2]);
        afr[kc][2] = *reinterpret_cast<const uint32_t*>(
            &sA[(wrow + r) * 72 + kb + cq * 2 + 8]);
        afr[kc][3] = *reinterpret_cast<const uint32_t*>(
            &sA[(wrow + r + 8) * 72 + kb + cq * 2 + 8]);
    }

#pragma unroll
    for (int nt = 0; nt < 8; nt++) {
        int nb = nt * 8;
        float acc[4] = {0.f, 0.f, 0.f, 0.f};
#pragma unroll
        for (int kc = 0; kc < 4; kc++) {
            int kb = kc * 16;
            uint32_t b0 = *reinterpret_cast<const uint32_t*>(
                &sWT[(nb + r) * 72 + kb + cq * 2]);
            uint32_t b1 = *reinterpret_cast<const uint32_t*>(
                &sWT[(nb + r) * 72 + kb + cq * 2 + 8]);
            asm volatile(
                "mma.sync.aligned.m16n8k16.row.col.f32.f16.f16.f32 "
                "{%0,%1,%2,%3}, {%4,%5,%6,%7}, {%8,%9}, {%0,%1,%2,%3};"
                : "+f"(acc[0]), "+f"(acc[1]), "+f"(acc[2]), "+f"(acc[3])
                : "r"(afr[kc][0]), "r"(afr[kc][1]),
                  "r"(afr[kc][2]), "r"(afr[kc][3]),
                  "r"(b0), "r"(b1));
        }
        int row = row0 + wrow + r;
        int col = nb + cq * 2;
        if (row < n_rows)
            *reinterpret_cast<__half2*>(C + (size_t)row * FDIM + col) =
                __floats2half2_rn(acc[0], acc[1]);
        if (row + 8 < n_rows)
            *reinterpret_cast<__half2*>(C + (size_t)(row + 8) * FDIM + col) =
                __floats2half2_rn(acc[2], acc[3]);
    }
}

// ---------------------------------------------------------------------------
extern "C" void kernel_launch(void* const* d_in, const int* in_sizes, int n_in,
                              void* d_out, int out_size)
{
    const float* x  = (const float*)d_in[0];
    const int*   ei = (const int*)d_in[1];     // int32 (JAX x64 disabled)
    const float* W1 = (const float*)d_in[2];
    const float* b1 = (const float*)d_in[3];
    const float* W2 = (const float*)d_in[4];
    const float* b2 = (const float*)d_in[5];
    float* out = (float*)d_out;

    const long long E = (long long)in_sizes[1] / 2;

    __half* g_hh_ptr;   cudaGetSymbolAddress((void**)&g_hh_ptr,   g_hh);
    __half* g_ah_ptr;   cudaGetSymbolAddress((void**)&g_ah_ptr,   g_ah);
    int*    g_degi_ptr; cudaGetSymbolAddress((void**)&g_degi_ptr, g_degi);

    const int SMS = 148;
    dim3 blk(256);

    const int gemm_grid = (NNODES + GROWS - 1) / GROWS;   // 782
    const int agg_grid  = SMS * 24;

    // ---- CSR build ----
    cudaMemsetAsync(g_degi_ptr, 0, NNODES * sizeof(int));
    hist_kernel<<<SMS * 8, blk>>>(ei, E);
    scan_reduce_kernel<<<NSCANBLK, SCAN_BLK>>>();   // also computes dinv
    scan_bsum_kernel<<<1, 128>>>();
    scan_write_kernel<<<NSCANBLK, SCAN_BLK>>>();
    fill_kernel<<<SMS * 8, blk>>>(ei, E);

    // ---- layer 1 ----
    gemm_mma_kernel<float><<<gemm_grid, blk>>>(x, W1, g_hh_ptr, NNODES);
    agg_kernel<__half><<<agg_grid, blk>>>(g_hh_ptr, b1, g_ah_ptr);

    // ---- layer 2 ----
    gemm_mma_kernel<__half><<<gemm_grid, blk>>>(g_ah_ptr, W2, g_hh_ptr, NNODES);
    agg_kernel<float><<<agg_grid, blk>>>(g_hh_ptr, b2, out);
}